// round 8
// baseline (speedup 1.0000x reference)
#include <cuda_runtime.h>
#include <cstdint>

// ---------------------------------------------------------------------------
// TTLinear: y[4096,4096] = x[4096,1024] @ W[1024,4096] + bias
// tcgen05 is NOT available in this harness (ptxas targets baseline sm_103,
// rejects all tcgen05/"a"-features). So: best-possible mma.sync tf32 path.
//
// vs R2 (272.8us total, GEMM 234us @ tensor=48%):
//  * x pre-rounded to tf32 once (k_x) -> no cvt in the GEMM mainloop
//  * both operands stored with k-groups permuted (0,4,1,5,2,6,3,7) so every
//    mma fragment (k,k+4) pair is one lds.64 -> LDS instr count halved
//  * W built transposed [N][K] so B fragments use the same lds.64 trick
// ---------------------------------------------------------------------------

#define TOKENS 4096
#define KDIM   1024
#define NDIM   4096

__device__ float g_G2[64 * 64 * 16];              // 256 KB
__device__ float g_G3[256 * 512 * 16];            // 8 MB
__device__ float g_Wt[(size_t)NDIM * KDIM];       // 16 MB, [N][K], k-permuted, tf32
__device__ float g_Xr[(size_t)TOKENS * KDIM];     // 16 MB, [M][K], k-permuted, tf32

__device__ __forceinline__ uint32_t f2tf32(float f) {
    uint32_t u; asm("cvt.rna.tf32.f32 %0, %1;" : "=r"(u) : "f"(f)); return u;
}

// ---------------- builders ----------------

// x -> tf32, k-permuted within each 8-group: new order (0,4,1,5,2,6,3,7)
__global__ void k_x(const float* __restrict__ x) {
    int g = blockIdx.x * 256 + threadIdx.x;            // 524288 8-float groups
    const float4* src = reinterpret_cast<const float4*>(x) + 2 * (size_t)g;
    float4 v0 = src[0], v1 = src[1];
    float4 p0, p1;
    p0.x = __uint_as_float(f2tf32(v0.x)); p0.y = __uint_as_float(f2tf32(v1.x));
    p0.z = __uint_as_float(f2tf32(v0.y)); p0.w = __uint_as_float(f2tf32(v1.y));
    p1.x = __uint_as_float(f2tf32(v0.z)); p1.y = __uint_as_float(f2tf32(v1.z));
    p1.z = __uint_as_float(f2tf32(v0.w)); p1.w = __uint_as_float(f2tf32(v1.w));
    float4* dst = reinterpret_cast<float4*>(g_Xr) + 2 * (size_t)g;
    dst[0] = p0; dst[1] = p1;
}

__global__ void k_g2(const float* __restrict__ c0, const float* __restrict__ c1) {
    int idx = blockIdx.x * 256 + threadIdx.x;          // 65536
    int r2 = idx & 15;
    int N2 = (idx >> 4) & 63;
    int M2 = idx >> 10;
    int m1 = M2 >> 3, m2 = M2 & 7, n1 = N2 >> 3, n2 = N2 & 7;
    float s = 0.f;
#pragma unroll
    for (int r1 = 0; r1 < 16; r1++)
        s += c0[(m1 * 8 + n1) * 16 + r1] * c1[((r1 * 8 + m2) * 8 + n2) * 16 + r2];
    g_G2[idx] = s;
}

__global__ void k_g3(const float* __restrict__ c2) {
    int idx = blockIdx.x * 256 + threadIdx.x;          // 2097152
    int r3 = idx & 15;
    int N3 = (idx >> 4) & 511;
    int M3 = idx >> 13;
    int N2 = N3 >> 3, n3 = N3 & 7, M2 = M3 >> 2, m3 = M3 & 3;
    const float* g2 = &g_G2[(M2 * 64 + N2) * 16];
    float s = 0.f;
#pragma unroll
    for (int r2 = 0; r2 < 16; r2++)
        s += g2[r2] * c2[((r2 * 4 + m3) * 8 + n3) * 16 + r3];
    g_G3[idx] = s;
}

// W^T builder: out-feature-major [N][K], tf32-rounded, k-permuted.
// in-feature f = M3*4 + m4 -> permuted column (M3>>1)*8 + 2*m4 + (M3&1)
__global__ void k_wt(const float* __restrict__ c3) {
    __shared__ float sc3[512];
    int t = threadIdx.x;
    sc3[t] = c3[t];
    sc3[t + 256] = c3[t + 256];
    __syncthreads();

    int idx = blockIdx.x * 256 + t;                    // 131072 = 256*512
    int N3 = idx & 511, M3 = idx >> 9;
    float g3[16];
    const float4* g3p = reinterpret_cast<const float4*>(&g_G3[((size_t)M3 * 512 + N3) * 16]);
#pragma unroll
    for (int r = 0; r < 4; r++) {
        float4 v = g3p[r];
        g3[4 * r] = v.x; g3[4 * r + 1] = v.y; g3[4 * r + 2] = v.z; g3[4 * r + 3] = v.w;
    }
    int kbase = (M3 >> 1) * 8 + (M3 & 1);              // permuted column base
#pragma unroll
    for (int n4 = 0; n4 < 8; n4++) {
        float acc[4] = {0.f, 0.f, 0.f, 0.f};
#pragma unroll
        for (int r3 = 0; r3 < 16; r3++) {
            float g = g3[r3];
#pragma unroll
            for (int m4 = 0; m4 < 4; m4++)
                acc[m4] += g * sc3[(r3 * 4 + m4) * 8 + n4];
        }
        int o = N3 * 8 + n4;
        float* wrow = &g_Wt[(size_t)o * KDIM];
#pragma unroll
        for (int m4 = 0; m4 < 4; m4++)
            wrow[kbase + 2 * m4] = __uint_as_float(f2tf32(acc[m4]));
    }
}

// ---------------- GEMM (mma.sync tf32, lds.64 fragments) ----------------

#define BM 128
#define BN 128
#define BK 32
#define RS 36                        // padded row stride (floats): 144B -> no conflicts
#define A_STAGE (BM * RS)            // 4608 floats
#define B_STAGE (BN * RS)            // 4608 floats
#define STAGE (A_STAGE + B_STAGE)
#define SMEM_BYTES (2 * STAGE * 4)   // 73728

__device__ __forceinline__ void cp_async16(void* s, const void* g) {
    uint32_t sa = (uint32_t)__cvta_generic_to_shared(s);
    asm volatile("cp.async.cg.shared.global [%0], [%1], 16;\n" :: "r"(sa), "l"(g));
}

__device__ __forceinline__ void mma8(float d[4], const uint32_t a[4], const uint32_t b[2]) {
    asm volatile(
        "mma.sync.aligned.m16n8k8.row.col.f32.tf32.tf32.f32 "
        "{%0,%1,%2,%3}, {%4,%5,%6,%7}, {%8,%9}, {%0,%1,%2,%3};\n"
        : "+f"(d[0]), "+f"(d[1]), "+f"(d[2]), "+f"(d[3])
        : "r"(a[0]), "r"(a[1]), "r"(a[2]), "r"(a[3]), "r"(b[0]), "r"(b[1]));
}

__global__ void __launch_bounds__(256)
gemm_kernel(const float* __restrict__ bias, float* __restrict__ out) {
    extern __shared__ float smem[];
    float* As = smem;                     // [2][BM][RS]  (row m, permuted k)
    float* Bs = smem + 2 * A_STAGE;       // [2][BN][RS]  (row n, permuted k)

    const int tid  = threadIdx.x;
    const int warp = tid >> 5, lane = tid & 31;
    const int wm = (warp >> 2) * 64;      // warp M offset (0/64)
    const int wn = (warp & 3) * 32;       // warp N offset (0/32/64/96)
    const int m0 = blockIdx.y * BM;
    const int n0 = blockIdx.x * BN;

    float acc[4][4][4];
#pragma unroll
    for (int i = 0; i < 4; i++)
#pragma unroll
        for (int j = 0; j < 4; j++)
#pragma unroll
            for (int k = 0; k < 4; k++) acc[i][j][k] = 0.f;

    auto load_stage = [&](int s, int k0) {
        float* A = As + s * A_STAGE;
        float* B = Bs + s * B_STAGE;
        // both tiles are 128 rows x 32 floats; copy 16B chunks (permuted-linear)
#pragma unroll
        for (int i = 0; i < 4; i++) {
            int q = i * 256 + tid;
            int r = q >> 3, c = (q & 7) << 2;
            cp_async16(&A[r * RS + c], &g_Xr[(size_t)(m0 + r) * KDIM + k0 + c]);
        }
#pragma unroll
        for (int i = 0; i < 4; i++) {
            int q = i * 256 + tid;
            int r = q >> 3, c = (q & 7) << 2;
            cp_async16(&B[r * RS + c], &g_Wt[(size_t)(n0 + r) * KDIM + k0 + c]);
        }
    };

    load_stage(0, 0);
    asm volatile("cp.async.commit_group;\n" ::);

    const int NT = KDIM / BK;             // 32
#pragma unroll 1
    for (int kt = 0; kt < NT; kt++) {
        if (kt + 1 < NT) {
            load_stage((kt + 1) & 1, (kt + 1) * BK);
            asm volatile("cp.async.commit_group;\n" ::);
            asm volatile("cp.async.wait_group 1;\n" ::);
        } else {
            asm volatile("cp.async.wait_group 0;\n" ::);
        }
        __syncthreads();

        const float* A = As + (kt & 1) * A_STAGE;
        const float* B = Bs + (kt & 1) * B_STAGE;

#pragma unroll
        for (int ks = 0; ks < 4; ks++) {
            // fragment loads: (k, k+4) pairs are adjacent (permuted layout)
            const int kf = ks * 8 + 2 * (lane & 3);     // float offset in row
            uint32_t af[4][4];
            const int ar = wm + (lane >> 2);
#pragma unroll
            for (int mi = 0; mi < 4; mi++) {
                const float* Ab = A + (ar + mi * 16) * RS + kf;
                uint2 lo = *reinterpret_cast<const uint2*>(Ab);            // {a0,a2}
                uint2 hi = *reinterpret_cast<const uint2*>(Ab + 8 * RS);   // {a1,a3}
                af[mi][0] = lo.x; af[mi][1] = hi.x; af[mi][2] = lo.y; af[mi][3] = hi.y;
            }
            uint32_t bf[4][2];
            const int br = wn + (lane >> 2);
#pragma unroll
            for (int ni = 0; ni < 4; ni++) {
                uint2 bb = *reinterpret_cast<const uint2*>(B + (br + ni * 8) * RS + kf);
                bf[ni][0] = bb.x; bf[ni][1] = bb.y;                        // {b0,b1}
            }
#pragma unroll
            for (int mi = 0; mi < 4; mi++)
#pragma unroll
                for (int ni = 0; ni < 4; ni++)
                    mma8(acc[mi][ni], af[mi], bf[ni]);
        }
        __syncthreads();
    }

    // epilogue: + bias, direct STG (same as R2)
#pragma unroll
    for (int mi = 0; mi < 4; mi++) {
        int row = m0 + wm + mi * 16 + (lane >> 2);
#pragma unroll
        for (int ni = 0; ni < 4; ni++) {
            int col = n0 + wn + ni * 8 + 2 * (lane & 3);
            float b0 = bias[col], b1 = bias[col + 1];
            float2 v0 = make_float2(acc[mi][ni][0] + b0, acc[mi][ni][1] + b1);
            float2 v1 = make_float2(acc[mi][ni][2] + b0, acc[mi][ni][3] + b1);
            *reinterpret_cast<float2*>(&out[(size_t)row * NDIM + col]) = v0;
            *reinterpret_cast<float2*>(&out[(size_t)(row + 8) * NDIM + col]) = v1;
        }
    }
}

// ---------------- launch ----------------

extern "C" void kernel_launch(void* const* d_in, const int* in_sizes, int n_in,
                              void* d_out, int out_size) {
    const float* x     = (const float*)d_in[0];
    const float* core0 = (const float*)d_in[1];
    const float* core1 = (const float*)d_in[2];
    const float* core2 = (const float*)d_in[3];
    const float* core3 = (const float*)d_in[4];
    const float* bias  = (const float*)d_in[5];
    float* out = (float*)d_out;

    k_x  <<<2048, 256>>>(x);
    k_g2 <<<256, 256>>>(core0, core1);
    k_g3 <<<8192, 256>>>(core2);
    k_wt <<<512, 256>>>(core3);

    cudaFuncSetAttribute(gemm_kernel,
                         cudaFuncAttributeMaxDynamicSharedMemorySize, SMEM_BYTES);
    gemm_kernel<<<dim3(NDIM / BN, TOKENS / BM), 256, SMEM_BYTES>>>(bias, out);
}

// round 9
// speedup vs baseline: 1.3467x; 1.3467x over previous
#include <cuda_runtime.h>
#include <cstdint>

// ---------------------------------------------------------------------------
// TTLinear: y[4096,4096] = x[4096,1024] @ W[1024,4096] + bias
// mma.sync tf32 path (tcgen05 rejected by this harness's ptxas target).
//
// R9 vs R8:
//  * GEMM: 128-thread CTAs, 2x2 warps of 64x64 (CUTLASS-style) -> fragment
//    LDS traffic per tile cut 1.5x; RS=40 padding -> conflict-free lds.64
//    (RS=36 had 2-way conflicts); 2 CTAs/SM.
//  * k_wt rewritten with coalesced 16B stores (was 8x write-amplified).
// Operand layouts unchanged from R8 (tf32-prerounded, k-permuted) — proven
// correct (rel_err identical to R2).
// ---------------------------------------------------------------------------

#define TOKENS 4096
#define KDIM   1024
#define NDIM   4096

__device__ float g_G2[64 * 64 * 16];              // 256 KB
__device__ float g_G3[256 * 512 * 16];            // 8 MB
__device__ float g_Wt[(size_t)NDIM * KDIM];       // 16 MB, [N][K], k-permuted, tf32
__device__ float g_Xr[(size_t)TOKENS * KDIM];     // 16 MB, [M][K], k-permuted, tf32

__device__ __forceinline__ uint32_t f2tf32(float f) {
    uint32_t u; asm("cvt.rna.tf32.f32 %0, %1;" : "=r"(u) : "f"(f)); return u;
}

// ---------------- builders ----------------

// x -> tf32, k-permuted within each 8-group: new order (0,4,1,5,2,6,3,7)
__global__ void k_x(const float* __restrict__ x) {
    int g = blockIdx.x * 256 + threadIdx.x;            // 524288 8-float groups
    const float4* src = reinterpret_cast<const float4*>(x) + 2 * (size_t)g;
    float4 v0 = src[0], v1 = src[1];
    float4 p0, p1;
    p0.x = __uint_as_float(f2tf32(v0.x)); p0.y = __uint_as_float(f2tf32(v1.x));
    p0.z = __uint_as_float(f2tf32(v0.y)); p0.w = __uint_as_float(f2tf32(v1.y));
    p1.x = __uint_as_float(f2tf32(v0.z)); p1.y = __uint_as_float(f2tf32(v1.z));
    p1.z = __uint_as_float(f2tf32(v0.w)); p1.w = __uint_as_float(f2tf32(v1.w));
    float4* dst = reinterpret_cast<float4*>(g_Xr) + 2 * (size_t)g;
    dst[0] = p0; dst[1] = p1;
}

__global__ void k_g2(const float* __restrict__ c0, const float* __restrict__ c1) {
    int idx = blockIdx.x * 256 + threadIdx.x;          // 65536
    int r2 = idx & 15;
    int N2 = (idx >> 4) & 63;
    int M2 = idx >> 10;
    int m1 = M2 >> 3, m2 = M2 & 7, n1 = N2 >> 3, n2 = N2 & 7;
    float s = 0.f;
#pragma unroll
    for (int r1 = 0; r1 < 16; r1++)
        s += c0[(m1 * 8 + n1) * 16 + r1] * c1[((r1 * 8 + m2) * 8 + n2) * 16 + r2];
    g_G2[idx] = s;
}

__global__ void k_g3(const float* __restrict__ c2) {
    int idx = blockIdx.x * 256 + threadIdx.x;          // 2097152
    int r3 = idx & 15;
    int N3 = (idx >> 4) & 511;
    int M3 = idx >> 13;
    int N2 = N3 >> 3, n3 = N3 & 7, M2 = M3 >> 2, m3 = M3 & 3;
    const float* g2 = &g_G2[(M2 * 64 + N2) * 16];
    float s = 0.f;
#pragma unroll
    for (int r2 = 0; r2 < 16; r2++)
        s += g2[r2] * c2[((r2 * 4 + m3) * 8 + n3) * 16 + r3];
    g_G3[idx] = s;
}

// W^T builder, coalesced: thread -> (out-feature o, permuted k-group g).
// Group g of row o holds: even slots 2*m4 from M3=2g, odd slots from M3=2g+1
// (identical permutation to R8:  col = (M3>>1)*8 + 2*m4 + (M3&1)).
// Each thread writes 8 contiguous floats (two st.128) -> fully coalesced.
__global__ void k_wt(const float* __restrict__ c3) {
    __shared__ float sc3[512];
    int t = threadIdx.x;
    sc3[t] = c3[t];
    sc3[t + 256] = c3[t + 256];
    __syncthreads();

    int idx = blockIdx.x * 256 + t;                    // 524288 = 4096 o x 128 g
    int g = idx & 127, o = idx >> 7;
    int N3 = o >> 3, n4 = o & 7;

    float outv[8];
#pragma unroll
    for (int h = 0; h < 2; h++) {
        int M3 = 2 * g + h;
        float g3[16];
        const float4* g3p =
            reinterpret_cast<const float4*>(&g_G3[((size_t)M3 * 512 + N3) * 16]);
#pragma unroll
        for (int r = 0; r < 4; r++) {
            float4 v = g3p[r];
            g3[4 * r] = v.x; g3[4 * r + 1] = v.y; g3[4 * r + 2] = v.z; g3[4 * r + 3] = v.w;
        }
        float acc[4] = {0.f, 0.f, 0.f, 0.f};
#pragma unroll
        for (int r3 = 0; r3 < 16; r3++) {
            float gg = g3[r3];
#pragma unroll
            for (int m4 = 0; m4 < 4; m4++)
                acc[m4] += gg * sc3[(r3 * 4 + m4) * 8 + n4];   // broadcast (n4 uniform/warp)
        }
#pragma unroll
        for (int m4 = 0; m4 < 4; m4++)
            outv[2 * m4 + h] = __uint_as_float(f2tf32(acc[m4]));
    }
    float4* dst = reinterpret_cast<float4*>(&g_Wt[(size_t)o * KDIM + g * 8]);
    dst[0] = make_float4(outv[0], outv[1], outv[2], outv[3]);
    dst[1] = make_float4(outv[4], outv[5], outv[6], outv[7]);
}

// ---------------- GEMM (mma.sync tf32, 64x64 warp tiles) ----------------

#define BM 128
#define BN 128
#define BK 32
#define RS 40                        // 160B row stride: conflict-free lds.64 phases
#define A_STAGE (BM * RS)            // 5120 floats
#define B_STAGE (BN * RS)
#define STAGE (A_STAGE + B_STAGE)    // 10240 floats = 40KB
#define SMEM_BYTES (2 * STAGE * 4)   // 81920 -> 2 CTAs/SM

__device__ __forceinline__ void cp_async16(void* s, const void* g) {
    uint32_t sa = (uint32_t)__cvta_generic_to_shared(s);
    asm volatile("cp.async.cg.shared.global [%0], [%1], 16;\n" :: "r"(sa), "l"(g));
}

__device__ __forceinline__ void mma8(float d[4], const uint32_t a[4], const uint32_t b[2]) {
    asm volatile(
        "mma.sync.aligned.m16n8k8.row.col.f32.tf32.tf32.f32 "
        "{%0,%1,%2,%3}, {%4,%5,%6,%7}, {%8,%9}, {%0,%1,%2,%3};\n"
        : "+f"(d[0]), "+f"(d[1]), "+f"(d[2]), "+f"(d[3])
        : "r"(a[0]), "r"(a[1]), "r"(a[2]), "r"(a[3]), "r"(b[0]), "r"(b[1]));
}

__global__ void __launch_bounds__(128, 2)
gemm_kernel(const float* __restrict__ bias, float* __restrict__ out) {
    extern __shared__ float smem[];
    float* As = smem;                     // [2][BM][RS]  (row m, permuted k)
    float* Bs = smem + 2 * A_STAGE;       // [2][BN][RS]  (row n, permuted k)

    const int tid  = threadIdx.x;
    const int warp = tid >> 5, lane = tid & 31;
    const int wm = (warp >> 1) * 64;      // warp M offset (0/64)
    const int wn = (warp & 1) * 64;       // warp N offset (0/64)
    const int m0 = blockIdx.y * BM;
    const int n0 = blockIdx.x * BN;

    float acc[4][8][4];                   // 64(M) x 64(N) per warp
#pragma unroll
    for (int i = 0; i < 4; i++)
#pragma unroll
        for (int j = 0; j < 8; j++)
#pragma unroll
            for (int k = 0; k < 4; k++) acc[i][j][k] = 0.f;

    auto load_stage = [&](int s, int k0) {
        float* A = As + s * A_STAGE;
        float* B = Bs + s * B_STAGE;
        // each tile: 128 rows x 32 floats; 128 threads x 8 x 16B
#pragma unroll
        for (int i = 0; i < 8; i++) {
            int q = i * 128 + tid;
            int r = q >> 3, c = (q & 7) << 2;
            cp_async16(&A[r * RS + c], &g_Xr[(size_t)(m0 + r) * KDIM + k0 + c]);
        }
#pragma unroll
        for (int i = 0; i < 8; i++) {
            int q = i * 128 + tid;
            int r = q >> 3, c = (q & 7) << 2;
            cp_async16(&B[r * RS + c], &g_Wt[(size_t)(n0 + r) * KDIM + k0 + c]);
        }
    };

    load_stage(0, 0);
    asm volatile("cp.async.commit_group;\n" ::);

    const int NT = KDIM / BK;             // 32
#pragma unroll 1
    for (int kt = 0; kt < NT; kt++) {
        if (kt + 1 < NT) {
            load_stage((kt + 1) & 1, (kt + 1) * BK);
            asm volatile("cp.async.commit_group;\n" ::);
            asm volatile("cp.async.wait_group 1;\n" ::);
        } else {
            asm volatile("cp.async.wait_group 0;\n" ::);
        }
        __syncthreads();

        const float* A = As + (kt & 1) * A_STAGE;
        const float* B = Bs + (kt & 1) * B_STAGE;

#pragma unroll
        for (int ks = 0; ks < 4; ks++) {
            const int kf = ks * 8 + 2 * (lane & 3);     // (k,k+4) pair adjacent
            uint32_t af[4][4];
            const int ar = wm + (lane >> 2);
#pragma unroll
            for (int mi = 0; mi < 4; mi++) {
                const float* Ab = A + (ar + mi * 16) * RS + kf;
                uint2 lo = *reinterpret_cast<const uint2*>(Ab);            // {a0,a2}
                uint2 hi = *reinterpret_cast<const uint2*>(Ab + 8 * RS);   // {a1,a3}
                af[mi][0] = lo.x; af[mi][1] = hi.x; af[mi][2] = lo.y; af[mi][3] = hi.y;
            }
            uint32_t bf[8][2];
            const int br = wn + (lane >> 2);
#pragma unroll
            for (int ni = 0; ni < 8; ni++) {
                uint2 bb = *reinterpret_cast<const uint2*>(B + (br + ni * 8) * RS + kf);
                bf[ni][0] = bb.x; bf[ni][1] = bb.y;                        // {b0,b1}
            }
#pragma unroll
            for (int mi = 0; mi < 4; mi++)
#pragma unroll
                for (int ni = 0; ni < 8; ni++)
                    mma8(acc[mi][ni], af[mi], bf[ni]);
        }
        __syncthreads();
    }

    // epilogue: + bias, direct STG
#pragma unroll
    for (int mi = 0; mi < 4; mi++) {
        int row = m0 + wm + mi * 16 + (lane >> 2);
#pragma unroll
        for (int ni = 0; ni < 8; ni++) {
            int col = n0 + wn + ni * 8 + 2 * (lane & 3);
            float b0 = bias[col], b1 = bias[col + 1];
            float2 v0 = make_float2(acc[mi][ni][0] + b0, acc[mi][ni][1] + b1);
            float2 v1 = make_float2(acc[mi][ni][2] + b0, acc[mi][ni][3] + b1);
            *reinterpret_cast<float2*>(&out[(size_t)row * NDIM + col]) = v0;
            *reinterpret_cast<float2*>(&out[(size_t)(row + 8) * NDIM + col]) = v1;
        }
    }
}

// ---------------- launch ----------------

extern "C" void kernel_launch(void* const* d_in, const int* in_sizes, int n_in,
                              void* d_out, int out_size) {
    const float* x     = (const float*)d_in[0];
    const float* core0 = (const float*)d_in[1];
    const float* core1 = (const float*)d_in[2];
    const float* core2 = (const float*)d_in[3];
    const float* core3 = (const float*)d_in[4];
    const float* bias  = (const float*)d_in[5];
    float* out = (float*)d_out;

    k_x  <<<2048, 256>>>(x);
    k_g2 <<<256, 256>>>(core0, core1);
    k_g3 <<<8192, 256>>>(core2);
    k_wt <<<2048, 256>>>(core3);

    cudaFuncSetAttribute(gemm_kernel,
                         cudaFuncAttributeMaxDynamicSharedMemorySize, SMEM_BYTES);
    gemm_kernel<<<dim3(NDIM / BN, TOKENS / BM), 128, SMEM_BYTES>>>(bias, out);
}

// round 10
// speedup vs baseline: 1.4098x; 1.0468x over previous
#include <cuda_runtime.h>
#include <cstdint>

// ---------------------------------------------------------------------------
// TTLinear: y[4096,4096] = x[4096,1024] @ W[1024,4096] + bias
// mma.sync tf32 path (tcgen05 rejected by this harness's ptxas target).
//
// R10 vs R9 (227.4us):
//  * k_wt: one thread per (N3, k-group) computes all 8 n4 outputs ->
//    g_G3 read once instead of 8x (was 64MB through L1, now 8MB).
//  * g_G3 re-laid as [N3][M3][r3] so k_wt reads are contiguous; k_g3
//    thread map adjusted so its writes stay coalesced.
//  * GEMM unchanged (64x64 warp tiles, RS=40, lds.64 fragments, 2 CTA/SM).
// Arithmetic order per output unchanged -> rel_err must stay 2.9266e-4.
// ---------------------------------------------------------------------------

#define TOKENS 4096
#define KDIM   1024
#define NDIM   4096

__device__ float g_G2[64 * 64 * 16];              // 256 KB [M2][N2][r2]
__device__ float g_G3[512 * 256 * 16];            // 8 MB   [N3][M3][r3]
__device__ float g_Wt[(size_t)NDIM * KDIM];       // 16 MB, [N][K], k-permuted, tf32
__device__ float g_Xr[(size_t)TOKENS * KDIM];     // 16 MB, [M][K], k-permuted, tf32

__device__ __forceinline__ uint32_t f2tf32(float f) {
    uint32_t u; asm("cvt.rna.tf32.f32 %0, %1;" : "=r"(u) : "f"(f)); return u;
}

// ---------------- builders ----------------

// x -> tf32, k-permuted within each 8-group: new order (0,4,1,5,2,6,3,7)
__global__ void k_x(const float* __restrict__ x) {
    int g = blockIdx.x * 256 + threadIdx.x;            // 524288 8-float groups
    const float4* src = reinterpret_cast<const float4*>(x) + 2 * (size_t)g;
    float4 v0 = src[0], v1 = src[1];
    float4 p0, p1;
    p0.x = __uint_as_float(f2tf32(v0.x)); p0.y = __uint_as_float(f2tf32(v1.x));
    p0.z = __uint_as_float(f2tf32(v0.y)); p0.w = __uint_as_float(f2tf32(v1.y));
    p1.x = __uint_as_float(f2tf32(v0.z)); p1.y = __uint_as_float(f2tf32(v1.z));
    p1.z = __uint_as_float(f2tf32(v0.w)); p1.w = __uint_as_float(f2tf32(v1.w));
    float4* dst = reinterpret_cast<float4*>(g_Xr) + 2 * (size_t)g;
    dst[0] = p0; dst[1] = p1;
}

__global__ void k_g2(const float* __restrict__ c0, const float* __restrict__ c1) {
    int idx = blockIdx.x * 256 + threadIdx.x;          // 65536
    int r2 = idx & 15;
    int N2 = (idx >> 4) & 63;
    int M2 = idx >> 10;
    int m1 = M2 >> 3, m2 = M2 & 7, n1 = N2 >> 3, n2 = N2 & 7;
    float s = 0.f;
#pragma unroll
    for (int r1 = 0; r1 < 16; r1++)
        s += c0[(m1 * 8 + n1) * 16 + r1] * c1[((r1 * 8 + m2) * 8 + n2) * 16 + r2];
    g_G2[idx] = s;
}

// g_G3[N3][M3][r3]; thread map: r3 fastest -> coalesced writes.
__global__ void k_g3(const float* __restrict__ c2) {
    int idx = blockIdx.x * 256 + threadIdx.x;          // 2097152
    int r3 = idx & 15;
    int M3 = (idx >> 4) & 255;
    int N3 = idx >> 12;
    int N2 = N3 >> 3, n3 = N3 & 7, M2 = M3 >> 2, m3 = M3 & 3;
    const float* g2 = &g_G2[(M2 * 64 + N2) * 16];
    float s = 0.f;
#pragma unroll
    for (int r2 = 0; r2 < 16; r2++)
        s += g2[r2] * c2[((r2 * 4 + m3) * 8 + n3) * 16 + r3];
    g_G3[idx] = s;                                     // idx == (N3*256+M3)*16+r3
}

// W^T builder: thread -> (N3, k-group g). Computes ALL 8 n4 rows for this
// (N3, g) so g_G3 is read exactly once. Permutation unchanged:
//   col = (M3>>1)*8 + 2*m4 + (M3&1),  M3 = 2g+h.
__global__ void __launch_bounds__(256)
k_wt(const float* __restrict__ c3) {
    __shared__ float sc3[512];
    int t = threadIdx.x;
    sc3[t] = c3[t];
    sc3[t + 256] = c3[t + 256];
    __syncthreads();

    int idx = blockIdx.x * 256 + t;                    // 65536 = 512 N3 x 128 g
    int g = idx & 127, N3 = idx >> 7;

    float outv[8][8];                                  // [n4][permuted 8 floats]
#pragma unroll
    for (int h = 0; h < 2; h++) {
        int M3 = 2 * g + h;
        float g3[16];
        const float4* g3p =
            reinterpret_cast<const float4*>(&g_G3[((size_t)N3 * 256 + M3) * 16]);
#pragma unroll
        for (int r = 0; r < 4; r++) {
            float4 v = g3p[r];
            g3[4 * r] = v.x; g3[4 * r + 1] = v.y; g3[4 * r + 2] = v.z; g3[4 * r + 3] = v.w;
        }
#pragma unroll
        for (int n4 = 0; n4 < 8; n4++) {
            float acc[4] = {0.f, 0.f, 0.f, 0.f};
#pragma unroll
            for (int r3 = 0; r3 < 16; r3++) {
                float gg = g3[r3];
#pragma unroll
                for (int m4 = 0; m4 < 4; m4++)
                    acc[m4] += gg * sc3[(r3 * 4 + m4) * 8 + n4];
            }
#pragma unroll
            for (int m4 = 0; m4 < 4; m4++)
                outv[n4][2 * m4 + h] = __uint_as_float(f2tf32(acc[m4]));
        }
    }
#pragma unroll
    for (int n4 = 0; n4 < 8; n4++) {
        float4* dst = reinterpret_cast<float4*>(
            &g_Wt[(size_t)(N3 * 8 + n4) * KDIM + g * 8]);
        dst[0] = make_float4(outv[n4][0], outv[n4][1], outv[n4][2], outv[n4][3]);
        dst[1] = make_float4(outv[n4][4], outv[n4][5], outv[n4][6], outv[n4][7]);
    }
}

// ---------------- GEMM (mma.sync tf32, 64x64 warp tiles) ----------------

#define BM 128
#define BN 128
#define BK 32
#define RS 40                        // 160B row stride: conflict-free lds.64 phases
#define A_STAGE (BM * RS)
#define B_STAGE (BN * RS)
#define STAGE (A_STAGE + B_STAGE)
#define SMEM_BYTES (2 * STAGE * 4)   // 81920 -> 2 CTAs/SM

__device__ __forceinline__ void cp_async16(void* s, const void* g) {
    uint32_t sa = (uint32_t)__cvta_generic_to_shared(s);
    asm volatile("cp.async.cg.shared.global [%0], [%1], 16;\n" :: "r"(sa), "l"(g));
}

__device__ __forceinline__ void mma8(float d[4], const uint32_t a[4], const uint32_t b[2]) {
    asm volatile(
        "mma.sync.aligned.m16n8k8.row.col.f32.tf32.tf32.f32 "
        "{%0,%1,%2,%3}, {%4,%5,%6,%7}, {%8,%9}, {%0,%1,%2,%3};\n"
        : "+f"(d[0]), "+f"(d[1]), "+f"(d[2]), "+f"(d[3])
        : "r"(a[0]), "r"(a[1]), "r"(a[2]), "r"(a[3]), "r"(b[0]), "r"(b[1]));
}

__global__ void __launch_bounds__(128, 2)
gemm_kernel(const float* __restrict__ bias, float* __restrict__ out) {
    extern __shared__ float smem[];
    float* As = smem;                     // [2][BM][RS]  (row m, permuted k)
    float* Bs = smem + 2 * A_STAGE;       // [2][BN][RS]  (row n, permuted k)

    const int tid  = threadIdx.x;
    const int warp = tid >> 5, lane = tid & 31;
    const int wm = (warp >> 1) * 64;      // warp M offset (0/64)
    const int wn = (warp & 1) * 64;       // warp N offset (0/64)
    const int m0 = blockIdx.y * BM;
    const int n0 = blockIdx.x * BN;

    float acc[4][8][4];                   // 64(M) x 64(N) per warp
#pragma unroll
    for (int i = 0; i < 4; i++)
#pragma unroll
        for (int j = 0; j < 8; j++)
#pragma unroll
            for (int k = 0; k < 4; k++) acc[i][j][k] = 0.f;

    auto load_stage = [&](int s, int k0) {
        float* A = As + s * A_STAGE;
        float* B = Bs + s * B_STAGE;
#pragma unroll
        for (int i = 0; i < 8; i++) {
            int q = i * 128 + tid;
            int r = q >> 3, c = (q & 7) << 2;
            cp_async16(&A[r * RS + c], &g_Xr[(size_t)(m0 + r) * KDIM + k0 + c]);
        }
#pragma unroll
        for (int i = 0; i < 8; i++) {
            int q = i * 128 + tid;
            int r = q >> 3, c = (q & 7) << 2;
            cp_async16(&B[r * RS + c], &g_Wt[(size_t)(n0 + r) * KDIM + k0 + c]);
        }
    };

    load_stage(0, 0);
    asm volatile("cp.async.commit_group;\n" ::);

    const int NT = KDIM / BK;             // 32
#pragma unroll 1
    for (int kt = 0; kt < NT; kt++) {
        if (kt + 1 < NT) {
            load_stage((kt + 1) & 1, (kt + 1) * BK);
            asm volatile("cp.async.commit_group;\n" ::);
            asm volatile("cp.async.wait_group 1;\n" ::);
        } else {
            asm volatile("cp.async.wait_group 0;\n" ::);
        }
        __syncthreads();

        const float* A = As + (kt & 1) * A_STAGE;
        const float* B = Bs + (kt & 1) * B_STAGE;

#pragma unroll
        for (int ks = 0; ks < 4; ks++) {
            const int kf = ks * 8 + 2 * (lane & 3);     // (k,k+4) pair adjacent
            uint32_t af[4][4];
            const int ar = wm + (lane >> 2);
#pragma unroll
            for (int mi = 0; mi < 4; mi++) {
                const float* Ab = A + (ar + mi * 16) * RS + kf;
                uint2 lo = *reinterpret_cast<const uint2*>(Ab);            // {a0,a2}
                uint2 hi = *reinterpret_cast<const uint2*>(Ab + 8 * RS);   // {a1,a3}
                af[mi][0] = lo.x; af[mi][1] = hi.x; af[mi][2] = lo.y; af[mi][3] = hi.y;
            }
            uint32_t bf[8][2];
            const int br = wn + (lane >> 2);
#pragma unroll
            for (int ni = 0; ni < 8; ni++) {
                uint2 bb = *reinterpret_cast<const uint2*>(B + (br + ni * 8) * RS + kf);
                bf[ni][0] = bb.x; bf[ni][1] = bb.y;                        // {b0,b1}
            }
#pragma unroll
            for (int mi = 0; mi < 4; mi++)
#pragma unroll
                for (int ni = 0; ni < 8; ni++)
                    mma8(acc[mi][ni], af[mi], bf[ni]);
        }
        __syncthreads();
    }

    // epilogue: + bias, direct STG
#pragma unroll
    for (int mi = 0; mi < 4; mi++) {
        int row = m0 + wm + mi * 16 + (lane >> 2);
#pragma unroll
        for (int ni = 0; ni < 8; ni++) {
            int col = n0 + wn + ni * 8 + 2 * (lane & 3);
            float b0 = bias[col], b1 = bias[col + 1];
            float2 v0 = make_float2(acc[mi][ni][0] + b0, acc[mi][ni][1] + b1);
            float2 v1 = make_float2(acc[mi][ni][2] + b0, acc[mi][ni][3] + b1);
            *reinterpret_cast<float2*>(&out[(size_t)row * NDIM + col]) = v0;
            *reinterpret_cast<float2*>(&out[(size_t)(row + 8) * NDIM + col]) = v1;
        }
    }
}

// ---------------- launch ----------------

extern "C" void kernel_launch(void* const* d_in, const int* in_sizes, int n_in,
                              void* d_out, int out_size) {
    const float* x     = (const float*)d_in[0];
    const float* core0 = (const float*)d_in[1];
    const float* core1 = (const float*)d_in[2];
    const float* core2 = (const float*)d_in[3];
    const float* core3 = (const float*)d_in[4];
    const float* bias  = (const float*)d_in[5];
    float* out = (float*)d_out;

    k_x  <<<2048, 256>>>(x);
    k_g2 <<<256, 256>>>(core0, core1);
    k_g3 <<<8192, 256>>>(core2);
    k_wt <<<256, 256>>>(core3);

    cudaFuncSetAttribute(gemm_kernel,
                         cudaFuncAttributeMaxDynamicSharedMemorySize, SMEM_BYTES);
    gemm_kernel<<<dim3(NDIM / BN, TOKENS / BM), 128, SMEM_BYTES>>>(bias, out);
}

// round 11
// speedup vs baseline: 1.4365x; 1.0189x over previous
#include <cuda_runtime.h>
#include <cstdint>

// ---------------------------------------------------------------------------
// TTLinear: y[4096,4096] = x[4096,1024] @ W[1024,4096] + bias
// mma.sync tf32 path (tcgen05 rejected by this harness's ptxas target).
//
// R11 vs R10 (217.2us):
//  * GEMM: XOR-swizzled smem tiles (RS=32, chunk' = chunk ^ ((row&3)<<1))
//    instead of RS=40 padding -> stage 40KB->32KB, CTA smem 80KB->64KB,
//    __launch_bounds__(128,3) -> 3 CTAs/SM (12 warps/SM latency hiding).
//    Swizzle verified conflict-free for the lds.64 fragment phases.
//  * k_wt: n4 split across 4 threads (2 rows each), g fastest in lane ->
//    grid 256->1024 blocks, coalesced 1KB store runs. Fixes occ=19%.
// Arithmetic per output unchanged -> rel_err must stay 2.9266e-4.
// ---------------------------------------------------------------------------

#define TOKENS 4096
#define KDIM   1024
#define NDIM   4096

__device__ float g_G2[64 * 64 * 16];              // 256 KB [M2][N2][r2]
__device__ float g_G3[512 * 256 * 16];            // 8 MB   [N3][M3][r3]
__device__ float g_Wt[(size_t)NDIM * KDIM];       // 16 MB, [N][K], k-permuted, tf32
__device__ float g_Xr[(size_t)TOKENS * KDIM];     // 16 MB, [M][K], k-permuted, tf32

__device__ __forceinline__ uint32_t f2tf32(float f) {
    uint32_t u; asm("cvt.rna.tf32.f32 %0, %1;" : "=r"(u) : "f"(f)); return u;
}

// ---------------- builders ----------------

// x -> tf32, k-permuted within each 8-group: new order (0,4,1,5,2,6,3,7)
__global__ void k_x(const float* __restrict__ x) {
    int g = blockIdx.x * 256 + threadIdx.x;            // 524288 8-float groups
    const float4* src = reinterpret_cast<const float4*>(x) + 2 * (size_t)g;
    float4 v0 = src[0], v1 = src[1];
    float4 p0, p1;
    p0.x = __uint_as_float(f2tf32(v0.x)); p0.y = __uint_as_float(f2tf32(v1.x));
    p0.z = __uint_as_float(f2tf32(v0.y)); p0.w = __uint_as_float(f2tf32(v1.y));
    p1.x = __uint_as_float(f2tf32(v0.z)); p1.y = __uint_as_float(f2tf32(v1.z));
    p1.z = __uint_as_float(f2tf32(v0.w)); p1.w = __uint_as_float(f2tf32(v1.w));
    float4* dst = reinterpret_cast<float4*>(g_Xr) + 2 * (size_t)g;
    dst[0] = p0; dst[1] = p1;
}

__global__ void k_g2(const float* __restrict__ c0, const float* __restrict__ c1) {
    int idx = blockIdx.x * 256 + threadIdx.x;          // 65536
    int r2 = idx & 15;
    int N2 = (idx >> 4) & 63;
    int M2 = idx >> 10;
    int m1 = M2 >> 3, m2 = M2 & 7, n1 = N2 >> 3, n2 = N2 & 7;
    float s = 0.f;
#pragma unroll
    for (int r1 = 0; r1 < 16; r1++)
        s += c0[(m1 * 8 + n1) * 16 + r1] * c1[((r1 * 8 + m2) * 8 + n2) * 16 + r2];
    g_G2[idx] = s;
}

// g_G3[N3][M3][r3]; thread map: r3 fastest -> coalesced writes.
__global__ void k_g3(const float* __restrict__ c2) {
    int idx = blockIdx.x * 256 + threadIdx.x;          // 2097152
    int r3 = idx & 15;
    int M3 = (idx >> 4) & 255;
    int N3 = idx >> 12;
    int N2 = N3 >> 3, n3 = N3 & 7, M2 = M3 >> 2, m3 = M3 & 3;
    const float* g2 = &g_G2[(M2 * 64 + N2) * 16];
    float s = 0.f;
#pragma unroll
    for (int r2 = 0; r2 < 16; r2++)
        s += g2[r2] * c2[((r2 * 4 + m3) * 8 + n3) * 16 + r3];
    g_G3[idx] = s;                                     // idx == (N3*256+M3)*16+r3
}

// W^T builder: thread -> (N3, n4-pair np, k-group g); g fastest across lanes
// so stores are coalesced 1KB runs per warp. Each thread computes n4 = 2np,
// 2np+1 for its (N3, g). Permutation unchanged:
//   col = (M3>>1)*8 + 2*m4 + (M3&1),  M3 = 2g+h.
__global__ void __launch_bounds__(256)
k_wt(const float* __restrict__ c3) {
    __shared__ float sc3[512];
    int t = threadIdx.x;
    sc3[t] = c3[t];
    sc3[t + 256] = c3[t + 256];
    __syncthreads();

    int idx = blockIdx.x * 256 + t;        // 262144 = 512 N3 x 4 np x 128 g
    int g  = idx & 127;
    int np = (idx >> 7) & 3;
    int N3 = idx >> 9;

    float outv[2][8];                      // [n4 within pair][permuted 8 floats]
#pragma unroll
    for (int h = 0; h < 2; h++) {
        int M3 = 2 * g + h;
        float g3[16];
        const float4* g3p =
            reinterpret_cast<const float4*>(&g_G3[((size_t)N3 * 256 + M3) * 16]);
#pragma unroll
        for (int r = 0; r < 4; r++) {
            float4 v = g3p[r];
            g3[4 * r] = v.x; g3[4 * r + 1] = v.y; g3[4 * r + 2] = v.z; g3[4 * r + 3] = v.w;
        }
#pragma unroll
        for (int q = 0; q < 2; q++) {
            int n4 = 2 * np + q;
            float acc[4] = {0.f, 0.f, 0.f, 0.f};
#pragma unroll
            for (int r3 = 0; r3 < 16; r3++) {
                float gg = g3[r3];
#pragma unroll
                for (int m4 = 0; m4 < 4; m4++)
                    acc[m4] += gg * sc3[(r3 * 4 + m4) * 8 + n4];
            }
#pragma unroll
            for (int m4 = 0; m4 < 4; m4++)
                outv[q][2 * m4 + h] = __uint_as_float(f2tf32(acc[m4]));
        }
    }
#pragma unroll
    for (int q = 0; q < 2; q++) {
        int n4 = 2 * np + q;
        float4* dst = reinterpret_cast<float4*>(
            &g_Wt[(size_t)(N3 * 8 + n4) * KDIM + g * 8]);
        dst[0] = make_float4(outv[q][0], outv[q][1], outv[q][2], outv[q][3]);
        dst[1] = make_float4(outv[q][4], outv[q][5], outv[q][6], outv[q][7]);
    }
}

// ---------------- GEMM (mma.sync tf32, 64x64 warp tiles, XOR swizzle) -------

#define BM 128
#define BN 128
#define BK 32
#define RS 32                        // no padding; XOR swizzle instead
#define A_STAGE (BM * RS)            // 4096 floats = 16KB
#define B_STAGE (BN * RS)
#define STAGE (A_STAGE + B_STAGE)    // 32KB
#define SMEM_BYTES (2 * STAGE * 4)   // 65536 -> 3 CTAs/SM

__device__ __forceinline__ void cp_async16(void* s, const void* g) {
    uint32_t sa = (uint32_t)__cvta_generic_to_shared(s);
    asm volatile("cp.async.cg.shared.global [%0], [%1], 16;\n" :: "r"(sa), "l"(g));
}

__device__ __forceinline__ void mma8(float d[4], const uint32_t a[4], const uint32_t b[2]) {
    asm volatile(
        "mma.sync.aligned.m16n8k8.row.col.f32.tf32.tf32.f32 "
        "{%0,%1,%2,%3}, {%4,%5,%6,%7}, {%8,%9}, {%0,%1,%2,%3};\n"
        : "+f"(d[0]), "+f"(d[1]), "+f"(d[2]), "+f"(d[3])
        : "r"(a[0]), "r"(a[1]), "r"(a[2]), "r"(a[3]), "r"(b[0]), "r"(b[1]));
}

__global__ void __launch_bounds__(128, 3)
gemm_kernel(const float* __restrict__ bias, float* __restrict__ out) {
    extern __shared__ float smem[];
    float* As = smem;                     // [2][BM][32]  swizzled
    float* Bs = smem + 2 * A_STAGE;       // [2][BN][32]  swizzled

    const int tid  = threadIdx.x;
    const int warp = tid >> 5, lane = tid & 31;
    const int wm = (warp >> 1) * 64;      // warp M offset (0/64)
    const int wn = (warp & 1) * 64;       // warp N offset (0/64)
    const int m0 = blockIdx.y * BM;
    const int n0 = blockIdx.x * BN;
    const int rl = lane >> 2;             // fragment row-in-group 0..7
    const int jl = lane & 3;

    float acc[4][8][4];                   // 64(M) x 64(N) per warp
#pragma unroll
    for (int i = 0; i < 4; i++)
#pragma unroll
        for (int j = 0; j < 8; j++)
#pragma unroll
            for (int k = 0; k < 4; k++) acc[i][j][k] = 0.f;

    // store: chunk ch (16B) of row r lands at chunk ch ^ ((r&3)<<1)
    auto load_stage = [&](int s, int k0) {
        float* A = As + s * A_STAGE;
        float* B = Bs + s * B_STAGE;
#pragma unroll
        for (int i = 0; i < 8; i++) {
            int q = i * 128 + tid;
            int r = q >> 3, ch = q & 7;
            int sw = r * 32 + ((ch ^ ((r & 3) << 1)) << 2);
            cp_async16(&A[sw], &g_Xr[(size_t)(m0 + r) * KDIM + k0 + ch * 4]);
        }
#pragma unroll
        for (int i = 0; i < 8; i++) {
            int q = i * 128 + tid;
            int r = q >> 3, ch = q & 7;
            int sw = r * 32 + ((ch ^ ((r & 3) << 1)) << 2);
            cp_async16(&B[sw], &g_Wt[(size_t)(n0 + r) * KDIM + k0 + ch * 4]);
        }
    };

    load_stage(0, 0);
    asm volatile("cp.async.commit_group;\n" ::);

    const int NT = KDIM / BK;             // 32
#pragma unroll 1
    for (int kt = 0; kt < NT; kt++) {
        if (kt + 1 < NT) {
            load_stage((kt + 1) & 1, (kt + 1) * BK);
            asm volatile("cp.async.commit_group;\n" ::);
            asm volatile("cp.async.wait_group 1;\n" ::);
        } else {
            asm volatile("cp.async.wait_group 0;\n" ::);
        }
        __syncthreads();

        const float* A = As + (kt & 1) * A_STAGE;
        const float* B = Bs + (kt & 1) * B_STAGE;

#pragma unroll
        for (int ks = 0; ks < 4; ks++) {
            // logical float col kf = ks*8 + 2*jl; chunk = kf>>2, sub = kf&3.
            // swizzled in-row offset (same key for A and B: rows ≡ rl mod 4)
            const int xpart = (((2 * ks + (jl >> 1)) ^ ((rl & 3) << 1)) << 2)
                              + 2 * (jl & 1);
            uint32_t af[4][4];
            const float* Ab0 = A + (wm + rl) * 32 + xpart;
#pragma unroll
            for (int mi = 0; mi < 4; mi++) {
                uint2 lo = *reinterpret_cast<const uint2*>(Ab0 + mi * 16 * 32);
                uint2 hi = *reinterpret_cast<const uint2*>(Ab0 + mi * 16 * 32 + 8 * 32);
                af[mi][0] = lo.x; af[mi][1] = hi.x; af[mi][2] = lo.y; af[mi][3] = hi.y;
            }
            uint32_t bf[8][2];
            const float* Bb0 = B + (wn + rl) * 32 + xpart;
#pragma unroll
            for (int ni = 0; ni < 8; ni++) {
                uint2 bb = *reinterpret_cast<const uint2*>(Bb0 + ni * 8 * 32);
                bf[ni][0] = bb.x; bf[ni][1] = bb.y;
            }
#pragma unroll
            for (int mi = 0; mi < 4; mi++)
#pragma unroll
                for (int ni = 0; ni < 8; ni++)
                    mma8(acc[mi][ni], af[mi], bf[ni]);
        }
        __syncthreads();
    }

    // epilogue: + bias, direct STG
#pragma unroll
    for (int mi = 0; mi < 4; mi++) {
        int row = m0 + wm + mi * 16 + rl;
#pragma unroll
        for (int ni = 0; ni < 8; ni++) {
            int col = n0 + wn + ni * 8 + 2 * jl;
            float b0 = bias[col], b1 = bias[col + 1];
            float2 v0 = make_float2(acc[mi][ni][0] + b0, acc[mi][ni][1] + b1);
            float2 v1 = make_float2(acc[mi][ni][2] + b0, acc[mi][ni][3] + b1);
            *reinterpret_cast<float2*>(&out[(size_t)row * NDIM + col]) = v0;
            *reinterpret_cast<float2*>(&out[(size_t)(row + 8) * NDIM + col]) = v1;
        }
    }
}

// ---------------- launch ----------------

extern "C" void kernel_launch(void* const* d_in, const int* in_sizes, int n_in,
                              void* d_out, int out_size) {
    const float* x     = (const float*)d_in[0];
    const float* core0 = (const float*)d_in[1];
    const float* core1 = (const float*)d_in[2];
    const float* core2 = (const float*)d_in[3];
    const float* core3 = (const float*)d_in[4];
    const float* bias  = (const float*)d_in[5];
    float* out = (float*)d_out;

    k_x  <<<2048, 256>>>(x);
    k_g2 <<<256, 256>>>(core0, core1);
    k_g3 <<<8192, 256>>>(core2);
    k_wt <<<1024, 256>>>(core3);

    cudaFuncSetAttribute(gemm_kernel,
                         cudaFuncAttributeMaxDynamicSharedMemorySize, SMEM_BYTES);
    gemm_kernel<<<dim3(NDIM / BN, TOKENS / BM), 128, SMEM_BYTES>>>(bias, out);
}

// round 12
// speedup vs baseline: 1.5258x; 1.0622x over previous
#include <cuda_runtime.h>
#include <cstdint>

// ---------------------------------------------------------------------------
// TTLinear: y[4096,4096] = x[4096,1024] @ W[1024,4096] + bias
// mma.sync tf32 path (tcgen05 rejected by this harness's ptxas target).
//
// R12 vs R11 (213.2us):
//  * GEMM: 3-stage cp.async pipeline, ONE __syncthreads per k-tile (slot
//    kt+2 == slot kt-1, whose readers all passed this iteration's sync).
//    Barriers per CTA 64->32, prefetch depth 2 tiles. 96KB smem -> 2 CTA/SM.
//  * k_wt: reverted to the R10 mapping (all 8 n4 per thread, grid 256) —
//    measured 13.2us vs R11's 17.6us.
// Arithmetic per output unchanged -> rel_err must stay 2.9266e-4.
// ---------------------------------------------------------------------------

#define TOKENS 4096
#define KDIM   1024
#define NDIM   4096

__device__ float g_G2[64 * 64 * 16];              // 256 KB [M2][N2][r2]
__device__ float g_G3[512 * 256 * 16];            // 8 MB   [N3][M3][r3]
__device__ float g_Wt[(size_t)NDIM * KDIM];       // 16 MB, [N][K], k-permuted, tf32
__device__ float g_Xr[(size_t)TOKENS * KDIM];     // 16 MB, [M][K], k-permuted, tf32

__device__ __forceinline__ uint32_t f2tf32(float f) {
    uint32_t u; asm("cvt.rna.tf32.f32 %0, %1;" : "=r"(u) : "f"(f)); return u;
}

// ---------------- builders ----------------

// x -> tf32, k-permuted within each 8-group: new order (0,4,1,5,2,6,3,7)
__global__ void k_x(const float* __restrict__ x) {
    int g = blockIdx.x * 256 + threadIdx.x;            // 524288 8-float groups
    const float4* src = reinterpret_cast<const float4*>(x) + 2 * (size_t)g;
    float4 v0 = src[0], v1 = src[1];
    float4 p0, p1;
    p0.x = __uint_as_float(f2tf32(v0.x)); p0.y = __uint_as_float(f2tf32(v1.x));
    p0.z = __uint_as_float(f2tf32(v0.y)); p0.w = __uint_as_float(f2tf32(v1.y));
    p1.x = __uint_as_float(f2tf32(v0.z)); p1.y = __uint_as_float(f2tf32(v1.z));
    p1.z = __uint_as_float(f2tf32(v0.w)); p1.w = __uint_as_float(f2tf32(v1.w));
    float4* dst = reinterpret_cast<float4*>(g_Xr) + 2 * (size_t)g;
    dst[0] = p0; dst[1] = p1;
}

__global__ void k_g2(const float* __restrict__ c0, const float* __restrict__ c1) {
    int idx = blockIdx.x * 256 + threadIdx.x;          // 65536
    int r2 = idx & 15;
    int N2 = (idx >> 4) & 63;
    int M2 = idx >> 10;
    int m1 = M2 >> 3, m2 = M2 & 7, n1 = N2 >> 3, n2 = N2 & 7;
    float s = 0.f;
#pragma unroll
    for (int r1 = 0; r1 < 16; r1++)
        s += c0[(m1 * 8 + n1) * 16 + r1] * c1[((r1 * 8 + m2) * 8 + n2) * 16 + r2];
    g_G2[idx] = s;
}

// g_G3[N3][M3][r3]; thread map: r3 fastest -> coalesced writes.
__global__ void k_g3(const float* __restrict__ c2) {
    int idx = blockIdx.x * 256 + threadIdx.x;          // 2097152
    int r3 = idx & 15;
    int M3 = (idx >> 4) & 255;
    int N3 = idx >> 12;
    int N2 = N3 >> 3, n3 = N3 & 7, M2 = M3 >> 2, m3 = M3 & 3;
    const float* g2 = &g_G2[(M2 * 64 + N2) * 16];
    float s = 0.f;
#pragma unroll
    for (int r2 = 0; r2 < 16; r2++)
        s += g2[r2] * c2[((r2 * 4 + m3) * 8 + n3) * 16 + r3];
    g_G3[idx] = s;                                     // idx == (N3*256+M3)*16+r3
}

// W^T builder (R10 mapping): thread -> (N3, k-group g); computes ALL 8 n4
// rows so g_G3 is read exactly once. Permutation:
//   col = (M3>>1)*8 + 2*m4 + (M3&1),  M3 = 2g+h.
__global__ void __launch_bounds__(256)
k_wt(const float* __restrict__ c3) {
    __shared__ float sc3[512];
    int t = threadIdx.x;
    sc3[t] = c3[t];
    sc3[t + 256] = c3[t + 256];
    __syncthreads();

    int idx = blockIdx.x * 256 + t;                    // 65536 = 512 N3 x 128 g
    int g = idx & 127, N3 = idx >> 7;

    float outv[8][8];                                  // [n4][permuted 8 floats]
#pragma unroll
    for (int h = 0; h < 2; h++) {
        int M3 = 2 * g + h;
        float g3[16];
        const float4* g3p =
            reinterpret_cast<const float4*>(&g_G3[((size_t)N3 * 256 + M3) * 16]);
#pragma unroll
        for (int r = 0; r < 4; r++) {
            float4 v = g3p[r];
            g3[4 * r] = v.x; g3[4 * r + 1] = v.y; g3[4 * r + 2] = v.z; g3[4 * r + 3] = v.w;
        }
#pragma unroll
        for (int n4 = 0; n4 < 8; n4++) {
            float acc[4] = {0.f, 0.f, 0.f, 0.f};
#pragma unroll
            for (int r3 = 0; r3 < 16; r3++) {
                float gg = g3[r3];
#pragma unroll
                for (int m4 = 0; m4 < 4; m4++)
                    acc[m4] += gg * sc3[(r3 * 4 + m4) * 8 + n4];
            }
#pragma unroll
            for (int m4 = 0; m4 < 4; m4++)
                outv[n4][2 * m4 + h] = __uint_as_float(f2tf32(acc[m4]));
        }
    }
#pragma unroll
    for (int n4 = 0; n4 < 8; n4++) {
        float4* dst = reinterpret_cast<float4*>(
            &g_Wt[(size_t)(N3 * 8 + n4) * KDIM + g * 8]);
        dst[0] = make_float4(outv[n4][0], outv[n4][1], outv[n4][2], outv[n4][3]);
        dst[1] = make_float4(outv[n4][4], outv[n4][5], outv[n4][6], outv[n4][7]);
    }
}

// ---------------- GEMM (mma.sync tf32, 3-stage, 1 sync/tile) ----------------

#define BM 128
#define BN 128
#define BK 32
#define RS 32                        // no padding; XOR swizzle
#define A_STAGE (BM * RS)            // 4096 floats = 16KB
#define B_STAGE (BN * RS)
#define STAGE (A_STAGE + B_STAGE)    // 32KB
#define NSTG 3
#define SMEM_BYTES (NSTG * STAGE * 4)   // 98304 -> 2 CTAs/SM

__device__ __forceinline__ void cp_async16(void* s, const void* g) {
    uint32_t sa = (uint32_t)__cvta_generic_to_shared(s);
    asm volatile("cp.async.cg.shared.global [%0], [%1], 16;\n" :: "r"(sa), "l"(g));
}

__device__ __forceinline__ void mma8(float d[4], const uint32_t a[4], const uint32_t b[2]) {
    asm volatile(
        "mma.sync.aligned.m16n8k8.row.col.f32.tf32.tf32.f32 "
        "{%0,%1,%2,%3}, {%4,%5,%6,%7}, {%8,%9}, {%0,%1,%2,%3};\n"
        : "+f"(d[0]), "+f"(d[1]), "+f"(d[2]), "+f"(d[3])
        : "r"(a[0]), "r"(a[1]), "r"(a[2]), "r"(a[3]), "r"(b[0]), "r"(b[1]));
}

__global__ void __launch_bounds__(128, 2)
gemm_kernel(const float* __restrict__ bias, float* __restrict__ out) {
    extern __shared__ float smem[];

    const int tid  = threadIdx.x;
    const int warp = tid >> 5, lane = tid & 31;
    const int wm = (warp >> 1) * 64;      // warp M offset (0/64)
    const int wn = (warp & 1) * 64;       // warp N offset (0/64)
    const int m0 = blockIdx.y * BM;
    const int n0 = blockIdx.x * BN;
    const int rl = lane >> 2;             // fragment row-in-group 0..7
    const int jl = lane & 3;

    float acc[4][8][4];                   // 64(M) x 64(N) per warp
#pragma unroll
    for (int i = 0; i < 4; i++)
#pragma unroll
        for (int j = 0; j < 8; j++)
#pragma unroll
            for (int k = 0; k < 4; k++) acc[i][j][k] = 0.f;

    // store: chunk ch (16B) of row r lands at chunk ch ^ ((r&3)<<1)
    auto load_stage = [&](int s, int k0) {
        float* A = smem + s * STAGE;
        float* B = A + A_STAGE;
#pragma unroll
        for (int i = 0; i < 8; i++) {
            int q = i * 128 + tid;
            int r = q >> 3, ch = q & 7;
            int sw = r * 32 + ((ch ^ ((r & 3) << 1)) << 2);
            cp_async16(&A[sw], &g_Xr[(size_t)(m0 + r) * KDIM + k0 + ch * 4]);
        }
#pragma unroll
        for (int i = 0; i < 8; i++) {
            int q = i * 128 + tid;
            int r = q >> 3, ch = q & 7;
            int sw = r * 32 + ((ch ^ ((r & 3) << 1)) << 2);
            cp_async16(&B[sw], &g_Wt[(size_t)(n0 + r) * KDIM + k0 + ch * 4]);
        }
    };

    load_stage(0, 0);
    asm volatile("cp.async.commit_group;\n" ::);
    load_stage(1, BK);
    asm volatile("cp.async.commit_group;\n" ::);

    const int NT = KDIM / BK;             // 32
    int s = 0, s2 = 2;                    // current slot, slot for kt+2
#pragma unroll 1
    for (int kt = 0; kt < NT; kt++) {
        // stage kt ready?  committed = min(kt+2,NT); need pending <= committed-(kt+1)
        if (kt < NT - 1)
            asm volatile("cp.async.wait_group 1;\n" ::);
        else
            asm volatile("cp.async.wait_group 0;\n" ::);
        __syncthreads();   // also releases slot s2 (== slot kt-1) for the load below

        const float* A = smem + s * STAGE;
        const float* B = A + A_STAGE;

#pragma unroll
        for (int ks = 0; ks < 4; ks++) {
            const int xpart = (((2 * ks + (jl >> 1)) ^ ((rl & 3) << 1)) << 2)
                              + 2 * (jl & 1);
            uint32_t af[4][4];
            const float* Ab0 = A + (wm + rl) * 32 + xpart;
#pragma unroll
            for (int mi = 0; mi < 4; mi++) {
                uint2 lo = *reinterpret_cast<const uint2*>(Ab0 + mi * 16 * 32);
                uint2 hi = *reinterpret_cast<const uint2*>(Ab0 + mi * 16 * 32 + 8 * 32);
                af[mi][0] = lo.x; af[mi][1] = hi.x; af[mi][2] = lo.y; af[mi][3] = hi.y;
            }
            uint32_t bf[8][2];
            const float* Bb0 = B + (wn + rl) * 32 + xpart;
#pragma unroll
            for (int ni = 0; ni < 8; ni++) {
                uint2 bb = *reinterpret_cast<const uint2*>(Bb0 + ni * 8 * 32);
                bf[ni][0] = bb.x; bf[ni][1] = bb.y;
            }
#pragma unroll
            for (int mi = 0; mi < 4; mi++)
#pragma unroll
                for (int ni = 0; ni < 8; ni++)
                    mma8(acc[mi][ni], af[mi], bf[ni]);
        }

        if (kt + 2 < NT) {
            load_stage(s2, (kt + 2) * BK);
            asm volatile("cp.async.commit_group;\n" ::);
        }
        s  = (s  == NSTG - 1) ? 0 : s + 1;
        s2 = (s2 == NSTG - 1) ? 0 : s2 + 1;
    }

    // epilogue: + bias, direct STG
#pragma unroll
    for (int mi = 0; mi < 4; mi++) {
        int row = m0 + wm + mi * 16 + rl;
#pragma unroll
        for (int ni = 0; ni < 8; ni++) {
            int col = n0 + wn + ni * 8 + 2 * jl;
            float b0 = bias[col], b1 = bias[col + 1];
            float2 v0 = make_float2(acc[mi][ni][0] + b0, acc[mi][ni][1] + b1);
            float2 v1 = make_float2(acc[mi][ni][2] + b0, acc[mi][ni][3] + b1);
            *reinterpret_cast<float2*>(&out[(size_t)row * NDIM + col]) = v0;
            *reinterpret_cast<float2*>(&out[(size_t)(row + 8) * NDIM + col]) = v1;
        }
    }
}

// ---------------- launch ----------------

extern "C" void kernel_launch(void* const* d_in, const int* in_sizes, int n_in,
                              void* d_out, int out_size) {
    const float* x     = (const float*)d_in[0];
    const float* core0 = (const float*)d_in[1];
    const float* core1 = (const float*)d_in[2];
    const float* core2 = (const float*)d_in[3];
    const float* core3 = (const float*)d_in[4];
    const float* bias  = (const float*)d_in[5];
    float* out = (float*)d_out;

    k_x  <<<2048, 256>>>(x);
    k_g2 <<<256, 256>>>(core0, core1);
    k_g3 <<<8192, 256>>>(core2);
    k_wt <<<256, 256>>>(core3);

    cudaFuncSetAttribute(gemm_kernel,
                         cudaFuncAttributeMaxDynamicSharedMemorySize, SMEM_BYTES);
    gemm_kernel<<<dim3(NDIM / BN, TOKENS / BM), 128, SMEM_BYTES>>>(bias, out);
}